// round 7
// baseline (speedup 1.0000x reference)
#include <cuda_runtime.h>
#include <math.h>
#include <stdint.h>

#define N_TOK 4096
#define CDIM 256
#define NH 8
#define HD 32
#define QSCALE (0.17677669529663687f * 1.4426950408889634f)  // 32^-0.5 * log2(e)

// ---- scratch (device globals) ----
__device__ float    g_q [NH * N_TOK * HD];     // fp32 [head][n][d]
__device__ uint32_t g_kf[NH * N_TOK * HD];     // tf32 fragment-order [head][key][p]
__device__ uint32_t g_vt[NH * N_TOK * HD];     // tf32 [head][tile64][half][d][vc]
__device__ float    g_ao[N_TOK * CDIM];
__device__ float    g_kmask[N_TOK];            // 0.f kept, -1e30f dropped
__device__ float    g_po[2][N_TOK][CDIM];      // split-K partial O (unnormalized)
__device__ float    g_pm[2][NH][N_TOK];        // split-K partial rowmax (log2 domain)
__device__ float    g_pl[2][NH][N_TOK];        // split-K partial rowsum

// ============================================================
__device__ __forceinline__ uint32_t f2tf(float f) {
    uint32_t r; asm("cvt.rna.tf32.f32 %0, %1;" : "=r"(r) : "f"(f)); return r;
}
__device__ __forceinline__ float ex2(float x) {
    float r; asm("ex2.approx.ftz.f32 %0, %1;" : "=f"(r) : "f"(x)); return r;
}
__device__ __forceinline__ void mma_tf32(float c[4], const uint32_t a[4],
                                         uint32_t b0, uint32_t b1) {
    asm volatile(
        "mma.sync.aligned.m16n8k8.row.col.f32.tf32.tf32.f32 "
        "{%0,%1,%2,%3},{%4,%5,%6,%7},{%8,%9},{%0,%1,%2,%3};"
        : "+f"(c[0]), "+f"(c[1]), "+f"(c[2]), "+f"(c[3])
        : "r"(a[0]), "r"(a[1]), "r"(a[2]), "r"(a[3]), "r"(b0), "r"(b1));
}
__device__ __forceinline__ void cp16(void* s, const void* g) {
    uint32_t sa = (uint32_t)__cvta_generic_to_shared(s);
    asm volatile("cp.async.cg.shared.global [%0], [%1], 16;\n" :: "r"(sa), "l"(g) : "memory");
}
__device__ __forceinline__ void cp8(void* s, const void* g) {
    uint32_t sa = (uint32_t)__cvta_generic_to_shared(s);
    asm volatile("cp.async.ca.shared.global [%0], [%1], 8;\n" :: "r"(sa), "l"(g) : "memory");
}
__device__ __forceinline__ void cp_commit() { asm volatile("cp.async.commit_group;\n" ::: "memory"); }
__device__ __forceinline__ void cp_wait1()  { asm volatile("cp.async.wait_group 1;\n" ::: "memory"); }
__device__ __forceinline__ void cp_wait0()  { asm volatile("cp.async.wait_group 0;\n" ::: "memory"); }

// ============================================================
// Keep mask: keep = 3x3 dilation of (dbz >= 15)
// ============================================================
__global__ void keep_kernel(const float* __restrict__ dbz) {
    int n = blockIdx.x * 256 + threadIdx.x;
    if (n >= N_TOK) return;
    int t   = n >> 10;
    int rem = n & 1023;
    int y   = rem >> 5;
    int x   = rem & 31;
    const float* d = dbz + t * 1024;
    bool k = false;
    #pragma unroll
    for (int dy = -1; dy <= 1; dy++) {
        int yy = y + dy;
        if (yy < 0 || yy >= 32) continue;
        #pragma unroll
        for (int dx = -1; dx <= 1; dx++) {
            int xx = x + dx;
            if (xx < 0 || xx >= 32) continue;
            k = k || (d[yy * 32 + xx] >= 15.0f);
        }
    }
    g_kmask[n] = k ? 0.0f : -1e30f;
}

// ============================================================
// Tensor-core tf32 GEMM: C[M,N] = A[M,256] * B[N,256]^T
// CTA tile 128x64, BK=32, 8 warps (4x2), warp tile 32x32.
// MODE 0: qkv -> q fp32, K tf32 fragment-order, V tf32 transposed tiles.
// MODE 1: proj epilogue (bias + querymask + residual).
// ============================================================
template <int MODE>
__global__ __launch_bounds__(256) void gemm_tc(
    const float* __restrict__ A, const float* __restrict__ B,
    const float* __restrict__ bias, const float* __restrict__ xres,
    float* __restrict__ out)
{
    __shared__ __align__(16) uint32_t As[128][36];
    __shared__ __align__(16) uint32_t Bs[64][36];

    const float* Ap = (MODE == 0) ? A : g_ao;

    const int tid  = threadIdx.x;
    const int warp = tid >> 5;
    const int lane = tid & 31;
    const int grp  = lane >> 2;
    const int tig  = lane & 3;
    const int wm   = warp >> 1;
    const int wn   = warp & 1;
    const int row0 = blockIdx.y * 128;
    const int col0 = blockIdx.x * 64;

    float acc[2][4][4];
    #pragma unroll
    for (int mi = 0; mi < 2; mi++)
        #pragma unroll
        for (int ni = 0; ni < 4; ni++)
            #pragma unroll
            for (int j = 0; j < 4; j++) acc[mi][ni][j] = 0.0f;

    for (int k0 = 0; k0 < CDIM; k0 += 32) {
        __syncthreads();
        #pragma unroll
        for (int t = 0; t < 4; t++) {
            int idx = tid + t * 256;
            int r = idx >> 3, kq = idx & 7;
            float4 v = *(const float4*)&Ap[(row0 + r) * CDIM + k0 + kq * 4];
            int cb = ((kq >> 1) << 1) | (kq & 1);
            As[r][cb]      = f2tf(v.x);
            As[r][cb + 8]  = f2tf(v.y);
            As[r][cb + 16] = f2tf(v.z);
            As[r][cb + 24] = f2tf(v.w);
        }
        #pragma unroll
        for (int t = 0; t < 2; t++) {
            int idx = tid + t * 256;
            int r = idx >> 3, kq = idx & 7;
            float4 v = *(const float4*)&B[(col0 + r) * CDIM + k0 + kq * 4];
            int cb = ((kq >> 1) << 1) | (kq & 1);
            Bs[r][cb]      = f2tf(v.x);
            Bs[r][cb + 8]  = f2tf(v.y);
            Bs[r][cb + 16] = f2tf(v.z);
            Bs[r][cb + 24] = f2tf(v.w);
        }
        __syncthreads();

        uint32_t alo[2][8], ahi[2][8], bb[4][8];
        #pragma unroll
        for (int mi = 0; mi < 2; mi++) {
            int r = wm * 32 + mi * 16 + grp;
            *(uint4*)&alo[mi][0] = *(const uint4*)&As[r][tig * 8];
            *(uint4*)&alo[mi][4] = *(const uint4*)&As[r][tig * 8 + 4];
            *(uint4*)&ahi[mi][0] = *(const uint4*)&As[r + 8][tig * 8];
            *(uint4*)&ahi[mi][4] = *(const uint4*)&As[r + 8][tig * 8 + 4];
        }
        #pragma unroll
        for (int ni = 0; ni < 4; ni++) {
            int c = wn * 32 + ni * 8 + grp;
            *(uint4*)&bb[ni][0] = *(const uint4*)&Bs[c][tig * 8];
            *(uint4*)&bb[ni][4] = *(const uint4*)&Bs[c][tig * 8 + 4];
        }
        #pragma unroll
        for (int kc = 0; kc < 4; kc++)
            #pragma unroll
            for (int mi = 0; mi < 2; mi++) {
                uint32_t a[4] = {alo[mi][kc * 2], ahi[mi][kc * 2],
                                 alo[mi][kc * 2 + 1], ahi[mi][kc * 2 + 1]};
                #pragma unroll
                for (int ni = 0; ni < 4; ni++)
                    mma_tf32(acc[mi][ni], a, bb[ni][kc * 2], bb[ni][kc * 2 + 1]);
            }
    }

    #pragma unroll
    for (int mi = 0; mi < 2; mi++) {
        int rA = row0 + wm * 32 + mi * 16 + grp;
        #pragma unroll
        for (int half = 0; half < 2; half++) {
            int n = rA + half * 8;
            #pragma unroll
            for (int ni = 0; ni < 4; ni++) {
                int c = col0 + wn * 32 + ni * 8 + 2 * tig;
                float v0 = acc[mi][ni][half * 2 + 0];
                float v1 = acc[mi][ni][half * 2 + 1];
                if (MODE == 0) {
                    int part = c >> 8;
                    int cc   = c & 255;
                    int hh   = cc >> 5;
                    int dd   = cc & 31;       // even
                    if (part == 0) {
                        *(float2*)&g_q[(hh * N_TOK + n) * HD + dd] = make_float2(v0, v1);
                    } else if (part == 1) {
                        int d1 = dd + 1;
                        int p0 = ((dd & 3) << 3) + 2 * (dd >> 3) + ((dd >> 2) & 1);
                        int p1 = ((d1 & 3) << 3) + 2 * (d1 >> 3) + ((d1 >> 2) & 1);
                        uint32_t* base = g_kf + (hh * N_TOK + n) * HD;
                        base[p0] = f2tf(v0);
                        base[p1] = f2tf(v1);
                    } else {
                        int tile = n >> 6, hv = (n >> 5) & 1, key = n & 31;
                        int vc = ((key & 3) << 3) | (((key >> 3) & 3) << 1) | ((key >> 2) & 1);
                        uint32_t* base = g_vt + ((hh * 64 + tile) * 2 + hv) * 1024 + dd * 32 + vc;
                        base[0]  = f2tf(v0);
                        base[32] = f2tf(v1);   // d+1 -> next row
                    }
                } else {
                    bool keep = (g_kmask[n] == 0.0f);
                    float2 bv = *(const float2*)&bias[c];
                    float2 xr = *(const float2*)&xres[n * CDIM + c];
                    float o0 = (keep ? (v0 + bv.x) : 0.0f) + xr.x;
                    float o1 = (keep ? (v1 + bv.y) : 0.0f) + xr.y;
                    *(float2*)&out[n * CDIM + c] = make_float2(o0, o1);
                }
            }
        }
    }
}

// ============================================================
// Flash attention, split-K x2, cp.async double-buffered.
// Grid (32 q-tiles, 8 heads, 2 splits), 256 threads = 8 warps x 16 q.
// ============================================================
#define NT_SPLIT 32      // 2048 keys per split / 64

__global__ __launch_bounds__(256) void flash_tc_kernel() {
    const int head = blockIdx.y;
    const int spl  = blockIdx.z;
    const int qt   = blockIdx.x * 128;
    const int tid  = threadIdx.x;
    const int warp = tid >> 5;
    const int lane = tid & 31;
    const int g8   = lane >> 2;
    const int tig  = lane & 3;
    const int kbase = spl * 2048;

    __shared__ __align__(16) uint32_t Ks[2][64][36];
    __shared__ __align__(16) uint32_t Vt[2][2][32][34];
    __shared__ __align__(16) float mk[2][64];

    const float* Q = g_q + head * N_TOK * HD;
    const uint32_t* KF = g_kf + head * N_TOK * HD;
    const uint32_t* VT = g_vt + head * N_TOK * HD;

    // --- Q A-fragments (one-time), pre-scaled by scale*log2e ---
    const int qr0 = qt + warp * 16 + g8;
    const int qr1 = qr0 + 8;
    uint32_t qa[4][4];
    #pragma unroll
    for (int kc = 0; kc < 4; kc++) {
        int c0 = kc * 8 + tig;
        qa[kc][0] = f2tf(Q[qr0 * HD + c0]     * QSCALE);
        qa[kc][1] = f2tf(Q[qr1 * HD + c0]     * QSCALE);
        qa[kc][2] = f2tf(Q[qr0 * HD + c0 + 4] * QSCALE);
        qa[kc][3] = f2tf(Q[qr1 * HD + c0 + 4] * QSCALE);
    }

    float m0 = -1e30f, m1 = -1e30f, l0 = 0.0f, l1 = 0.0f;
    float o[4][4];
    #pragma unroll
    for (int nb = 0; nb < 4; nb++)
        #pragma unroll
        for (int j = 0; j < 4; j++) o[nb][j] = 0.0f;

    const int srcA = (lane & 28) | (tig >> 1);
    const int srcB = srcA + 2;
    const bool oddt = (tig & 1);

    // ---- prologue stage (buf 0, tile 0) ----
    {
        #pragma unroll
        for (int t = 0; t < 2; t++) {
            int c = tid + t * 256;
            int key = c >> 3, ch = (c & 7) * 4;
            cp16(&Ks[0][key][ch], KF + (kbase + key) * HD + ch);
        }
        const uint32_t* vg = VT + (kbase >> 6) * 2048;
        #pragma unroll
        for (int t = 0; t < 4; t++) {
            int c = tid + t * 256;
            int hv = c >> 9, d = (c >> 4) & 31, pr = (c & 15) * 2;
            cp8(&Vt[0][hv][d][pr], vg + hv * 1024 + d * 32 + pr);
        }
        if (tid < 64) mk[0][tid] = g_kmask[kbase + tid];
        cp_commit();
    }

    for (int it = 0; it < NT_SPLIT; it++) {
        const int buf = it & 1;
        if (it + 1 < NT_SPLIT) {
            const int nb1 = buf ^ 1;
            const int ka = kbase + (it + 1) * 64;
            #pragma unroll
            for (int t = 0; t < 2; t++) {
                int c = tid + t * 256;
                int key = c >> 3, ch = (c & 7) * 4;
                cp16(&Ks[nb1][key][ch], KF + (ka + key) * HD + ch);
            }
            const uint32_t* vg = VT + (ka >> 6) * 2048;
            #pragma unroll
            for (int t = 0; t < 4; t++) {
                int c = tid + t * 256;
                int hv = c >> 9, d = (c >> 4) & 31, pr = (c & 15) * 2;
                cp8(&Vt[nb1][hv][d][pr], vg + hv * 1024 + d * 32 + pr);
            }
            if (tid < 64) mk[nb1][tid] = g_kmask[ka + tid];
            cp_commit();
            cp_wait1();
        } else {
            cp_wait0();
        }
        __syncthreads();

        // --- S = Q K^T ---
        float sc[8][4];
        #pragma unroll
        for (int nb = 0; nb < 8; nb++) {
            uint32_t kb[8];
            *(uint4*)&kb[0] = *(const uint4*)&Ks[buf][nb * 8 + g8][tig * 8];
            *(uint4*)&kb[4] = *(const uint4*)&Ks[buf][nb * 8 + g8][tig * 8 + 4];
            sc[nb][0] = sc[nb][1] = sc[nb][2] = sc[nb][3] = 0.0f;
            #pragma unroll
            for (int kc = 0; kc < 4; kc++)
                mma_tf32(sc[nb], qa[kc], kb[kc * 2], kb[kc * 2 + 1]);
            float ma = mk[buf][nb * 8 + 2 * tig];
            float mb = mk[buf][nb * 8 + 2 * tig + 1];
            sc[nb][0] += ma; sc[nb][1] += mb;
            sc[nb][2] += ma; sc[nb][3] += mb;
        }

        // --- online softmax ---
        float rm0 = -1e30f, rm1 = -1e30f;
        #pragma unroll
        for (int nb = 0; nb < 8; nb++) {
            rm0 = fmaxf(rm0, fmaxf(sc[nb][0], sc[nb][1]));
            rm1 = fmaxf(rm1, fmaxf(sc[nb][2], sc[nb][3]));
        }
        rm0 = fmaxf(rm0, __shfl_xor_sync(0xffffffffu, rm0, 1));
        rm0 = fmaxf(rm0, __shfl_xor_sync(0xffffffffu, rm0, 2));
        rm1 = fmaxf(rm1, __shfl_xor_sync(0xffffffffu, rm1, 1));
        rm1 = fmaxf(rm1, __shfl_xor_sync(0xffffffffu, rm1, 2));

        float mn0 = fmaxf(m0, rm0);
        float mn1 = fmaxf(m1, rm1);
        float corr0 = ex2(m0 - mn0);
        float corr1 = ex2(m1 - mn1);
        m0 = mn0; m1 = mn1;
        l0 *= corr0; l1 *= corr1;
        #pragma unroll
        for (int nb = 0; nb < 4; nb++) {
            o[nb][0] *= corr0; o[nb][1] *= corr0;
            o[nb][2] *= corr1; o[nb][3] *= corr1;
        }

        // --- P = 2^(S-m) ---
        uint32_t up[8][4];
        #pragma unroll
        for (int nb = 0; nb < 8; nb++) {
            float p0 = ex2(sc[nb][0] - mn0);
            float p1 = ex2(sc[nb][1] - mn0);
            float p2 = ex2(sc[nb][2] - mn1);
            float p3 = ex2(sc[nb][3] - mn1);
            l0 += p0 + p1;
            l1 += p2 + p3;
            up[nb][0] = f2tf(p0); up[nb][1] = f2tf(p1);
            up[nb][2] = f2tf(p2); up[nb][3] = f2tf(p3);
        }

        // --- O += P V ---
        #pragma unroll
        for (int kc = 0; kc < 8; kc++) {
            uint32_t s0 = __shfl_sync(0xffffffffu, up[kc][0], srcA);
            uint32_t s1 = __shfl_sync(0xffffffffu, up[kc][1], srcA);
            uint32_t s2 = __shfl_sync(0xffffffffu, up[kc][2], srcA);
            uint32_t s3 = __shfl_sync(0xffffffffu, up[kc][3], srcA);
            uint32_t t0 = __shfl_sync(0xffffffffu, up[kc][0], srcB);
            uint32_t t1 = __shfl_sync(0xffffffffu, up[kc][1], srcB);
            uint32_t t2 = __shfl_sync(0xffffffffu, up[kc][2], srcB);
            uint32_t t3 = __shfl_sync(0xffffffffu, up[kc][3], srcB);
            uint32_t pa[4];
            pa[0] = oddt ? s1 : s0;
            pa[1] = oddt ? s3 : s2;
            pa[2] = oddt ? t1 : t0;
            pa[3] = oddt ? t3 : t2;
            int hf = kc >> 2;
            int co = tig * 8 + ((kc & 3) << 1);
            #pragma unroll
            for (int nb = 0; nb < 4; nb++) {
                uint2 bv = *(const uint2*)&Vt[buf][hf][nb * 8 + g8][co];
                mma_tf32(o[nb], pa, bv.x, bv.y);
            }
        }
        __syncthreads();
    }

    // --- partial epilogue: unnormalized O + (m,l) ---
    l0 += __shfl_xor_sync(0xffffffffu, l0, 1);
    l0 += __shfl_xor_sync(0xffffffffu, l0, 2);
    l1 += __shfl_xor_sync(0xffffffffu, l1, 1);
    l1 += __shfl_xor_sync(0xffffffffu, l1, 2);

    if (tig == 0) {
        g_pm[spl][head][qr0] = m0;  g_pl[spl][head][qr0] = l0;
        g_pm[spl][head][qr1] = m1;  g_pl[spl][head][qr1] = l1;
    }
    #pragma unroll
    for (int nb = 0; nb < 4; nb++) {
        int col = head * HD + nb * 8 + 2 * tig;
        *(float2*)&g_po[spl][qr0][col] = make_float2(o[nb][0], o[nb][1]);
        *(float2*)&g_po[spl][qr1][col] = make_float2(o[nb][2], o[nb][3]);
    }
}

// ============================================================
// Split-K combine: g_ao = (po0*w0 + po1*w1) / (l0*w0 + l1*w1)
// ============================================================
__global__ __launch_bounds__(256) void combine_kernel() {
    int n = blockIdx.x;
    int c = threadIdx.x;
    int head = c >> 5;
    float m0 = g_pm[0][head][n], m1 = g_pm[1][head][n];
    float l0 = g_pl[0][head][n], l1 = g_pl[1][head][n];
    float ms = fmaxf(m0, m1);
    float w0 = ex2(m0 - ms), w1 = ex2(m1 - ms);
    float l  = l0 * w0 + l1 * w1;
    float inv = (l > 0.0f) ? (1.0f / l) : 0.0f;
    float v = g_po[0][n][c] * w0 + g_po[1][n][c] * w1;
    g_ao[n * CDIM + c] = v * inv;
}

// ============================================================
extern "C" void kernel_launch(void* const* d_in, const int* in_sizes, int n_in,
                              void* d_out, int out_size) {
    const float* x      = (const float*)d_in[0];
    const float* dbz    = (const float*)d_in[1];
    const float* qkv_w  = (const float*)d_in[2];
    const float* proj_w = (const float*)d_in[3];
    const float* proj_b = (const float*)d_in[4];
    float* out = (float*)d_out;

    keep_kernel<<<16, 256>>>(dbz);
    gemm_tc<0><<<dim3(768 / 64, N_TOK / 128), 256>>>(x, qkv_w, nullptr, nullptr, nullptr);
    flash_tc_kernel<<<dim3(N_TOK / 128, NH, 2), 256>>>();
    combine_kernel<<<N_TOK, 256>>>();
    gemm_tc<1><<<dim3(CDIM / 64, N_TOK / 128), 256>>>(nullptr, proj_w, proj_b, x, out);
}

// round 8
// speedup vs baseline: 1.5657x; 1.5657x over previous
#include <cuda_runtime.h>
#include <math.h>
#include <stdint.h>

#define N_TOK 4096
#define CDIM 256
#define NH 8
#define HD 32
#define QSCALE (0.17677669529663687f * 1.4426950408889634f)  // 32^-0.5 * log2(e)

// ---- scratch (device globals) ----
__device__ float    g_q [NH * N_TOK * HD];     // fp32 [head][n][d]
__device__ uint32_t g_kf[NH * N_TOK * HD];     // tf32 fragment-order [head][key][p]
__device__ uint32_t g_vt[NH * N_TOK * HD];     // tf32 [head][tile64][half][d][vc]
__device__ float    g_ao[N_TOK * CDIM];
__device__ float    g_kmask[N_TOK];            // 0.f kept, -1e30f dropped

// ============================================================
__device__ __forceinline__ uint32_t f2tf(float f) {
    uint32_t r; asm("cvt.rna.tf32.f32 %0, %1;" : "=r"(r) : "f"(f)); return r;
}
__device__ __forceinline__ float ex2(float x) {
    float r; asm("ex2.approx.ftz.f32 %0, %1;" : "=f"(r) : "f"(x)); return r;
}
__device__ __forceinline__ void mma_tf32(float c[4], const uint32_t a[4],
                                         uint32_t b0, uint32_t b1) {
    asm volatile(
        "mma.sync.aligned.m16n8k8.row.col.f32.tf32.tf32.f32 "
        "{%0,%1,%2,%3},{%4,%5,%6,%7},{%8,%9},{%0,%1,%2,%3};"
        : "+f"(c[0]), "+f"(c[1]), "+f"(c[2]), "+f"(c[3])
        : "r"(a[0]), "r"(a[1]), "r"(a[2]), "r"(a[3]), "r"(b0), "r"(b1));
}
__device__ __forceinline__ void cp16(void* s, const void* g) {
    uint32_t sa = (uint32_t)__cvta_generic_to_shared(s);
    asm volatile("cp.async.cg.shared.global [%0], [%1], 16;\n" :: "r"(sa), "l"(g) : "memory");
}
__device__ __forceinline__ void cp8(void* s, const void* g) {
    uint32_t sa = (uint32_t)__cvta_generic_to_shared(s);
    asm volatile("cp.async.ca.shared.global [%0], [%1], 8;\n" :: "r"(sa), "l"(g) : "memory");
}
__device__ __forceinline__ void cp_commit() { asm volatile("cp.async.commit_group;\n" ::: "memory"); }
__device__ __forceinline__ void cp_wait1()  { asm volatile("cp.async.wait_group 1;\n" ::: "memory"); }
__device__ __forceinline__ void cp_wait0()  { asm volatile("cp.async.wait_group 0;\n" ::: "memory"); }

// ============================================================
// Keep mask: keep = 3x3 dilation of (dbz >= 15)
// ============================================================
__global__ void keep_kernel(const float* __restrict__ dbz) {
    int n = blockIdx.x * 256 + threadIdx.x;
    if (n >= N_TOK) return;
    int t   = n >> 10;
    int rem = n & 1023;
    int y   = rem >> 5;
    int x   = rem & 31;
    const float* d = dbz + t * 1024;
    bool k = false;
    #pragma unroll
    for (int dy = -1; dy <= 1; dy++) {
        int yy = y + dy;
        if (yy < 0 || yy >= 32) continue;
        #pragma unroll
        for (int dx = -1; dx <= 1; dx++) {
            int xx = x + dx;
            if (xx < 0 || xx >= 32) continue;
            k = k || (d[yy * 32 + xx] >= 15.0f);
        }
    }
    g_kmask[n] = k ? 0.0f : -1e30f;
}

// ============================================================
// Tensor-core tf32 GEMM: C[M,N] = A[M,256] * B[N,256]^T
// CTA tile 128x64, BK=32, 8 warps (4x2), warp tile 32x32.
// MODE 0: qkv -> q fp32, K tf32 fragment-order, V tf32 transposed tiles.
// MODE 1: proj epilogue (bias + querymask + residual).
// ============================================================
template <int MODE>
__global__ __launch_bounds__(256) void gemm_tc(
    const float* __restrict__ A, const float* __restrict__ B,
    const float* __restrict__ bias, const float* __restrict__ xres,
    float* __restrict__ out)
{
    __shared__ __align__(16) uint32_t As[128][36];
    __shared__ __align__(16) uint32_t Bs[64][36];

    const float* Ap = (MODE == 0) ? A : g_ao;

    const int tid  = threadIdx.x;
    const int warp = tid >> 5;
    const int lane = tid & 31;
    const int grp  = lane >> 2;
    const int tig  = lane & 3;
    const int wm   = warp >> 1;
    const int wn   = warp & 1;
    const int row0 = blockIdx.y * 128;
    const int col0 = blockIdx.x * 64;

    float acc[2][4][4];
    #pragma unroll
    for (int mi = 0; mi < 2; mi++)
        #pragma unroll
        for (int ni = 0; ni < 4; ni++)
            #pragma unroll
            for (int j = 0; j < 4; j++) acc[mi][ni][j] = 0.0f;

    for (int k0 = 0; k0 < CDIM; k0 += 32) {
        __syncthreads();
        #pragma unroll
        for (int t = 0; t < 4; t++) {
            int idx = tid + t * 256;
            int r = idx >> 3, kq = idx & 7;
            float4 v = *(const float4*)&Ap[(row0 + r) * CDIM + k0 + kq * 4];
            int cb = ((kq >> 1) << 1) | (kq & 1);
            As[r][cb]      = f2tf(v.x);
            As[r][cb + 8]  = f2tf(v.y);
            As[r][cb + 16] = f2tf(v.z);
            As[r][cb + 24] = f2tf(v.w);
        }
        #pragma unroll
        for (int t = 0; t < 2; t++) {
            int idx = tid + t * 256;
            int r = idx >> 3, kq = idx & 7;
            float4 v = *(const float4*)&B[(col0 + r) * CDIM + k0 + kq * 4];
            int cb = ((kq >> 1) << 1) | (kq & 1);
            Bs[r][cb]      = f2tf(v.x);
            Bs[r][cb + 8]  = f2tf(v.y);
            Bs[r][cb + 16] = f2tf(v.z);
            Bs[r][cb + 24] = f2tf(v.w);
        }
        __syncthreads();

        uint32_t alo[2][8], ahi[2][8], bb[4][8];
        #pragma unroll
        for (int mi = 0; mi < 2; mi++) {
            int r = wm * 32 + mi * 16 + grp;
            *(uint4*)&alo[mi][0] = *(const uint4*)&As[r][tig * 8];
            *(uint4*)&alo[mi][4] = *(const uint4*)&As[r][tig * 8 + 4];
            *(uint4*)&ahi[mi][0] = *(const uint4*)&As[r + 8][tig * 8];
            *(uint4*)&ahi[mi][4] = *(const uint4*)&As[r + 8][tig * 8 + 4];
        }
        #pragma unroll
        for (int ni = 0; ni < 4; ni++) {
            int c = wn * 32 + ni * 8 + grp;
            *(uint4*)&bb[ni][0] = *(const uint4*)&Bs[c][tig * 8];
            *(uint4*)&bb[ni][4] = *(const uint4*)&Bs[c][tig * 8 + 4];
        }
        #pragma unroll
        for (int kc = 0; kc < 4; kc++)
            #pragma unroll
            for (int mi = 0; mi < 2; mi++) {
                uint32_t a[4] = {alo[mi][kc * 2], ahi[mi][kc * 2],
                                 alo[mi][kc * 2 + 1], ahi[mi][kc * 2 + 1]};
                #pragma unroll
                for (int ni = 0; ni < 4; ni++)
                    mma_tf32(acc[mi][ni], a, bb[ni][kc * 2], bb[ni][kc * 2 + 1]);
            }
    }

    #pragma unroll
    for (int mi = 0; mi < 2; mi++) {
        int rA = row0 + wm * 32 + mi * 16 + grp;
        #pragma unroll
        for (int half = 0; half < 2; half++) {
            int n = rA + half * 8;
            #pragma unroll
            for (int ni = 0; ni < 4; ni++) {
                int c = col0 + wn * 32 + ni * 8 + 2 * tig;
                float v0 = acc[mi][ni][half * 2 + 0];
                float v1 = acc[mi][ni][half * 2 + 1];
                if (MODE == 0) {
                    int part = c >> 8;
                    int cc   = c & 255;
                    int hh   = cc >> 5;
                    int dd   = cc & 31;       // even
                    if (part == 0) {
                        *(float2*)&g_q[(hh * N_TOK + n) * HD + dd] = make_float2(v0, v1);
                    } else if (part == 1) {
                        int d1 = dd + 1;
                        int p0 = ((dd & 3) << 3) + 2 * (dd >> 3) + ((dd >> 2) & 1);
                        int p1 = ((d1 & 3) << 3) + 2 * (d1 >> 3) + ((d1 >> 2) & 1);
                        uint32_t* base = g_kf + (hh * N_TOK + n) * HD;
                        base[p0] = f2tf(v0);
                        base[p1] = f2tf(v1);
                    } else {
                        int tile = n >> 6, hv = (n >> 5) & 1, key = n & 31;
                        int vc = ((key & 3) << 3) | (((key >> 3) & 3) << 1) | ((key >> 2) & 1);
                        uint32_t* base = g_vt + ((hh * 64 + tile) * 2 + hv) * 1024 + dd * 32 + vc;
                        base[0]  = f2tf(v0);
                        base[32] = f2tf(v1);   // d+1 -> next row
                    }
                } else {
                    bool keep = (g_kmask[n] == 0.0f);
                    float2 bv = *(const float2*)&bias[c];
                    float2 xr = *(const float2*)&xres[n * CDIM + c];
                    float o0 = (keep ? (v0 + bv.x) : 0.0f) + xr.x;
                    float o1 = (keep ? (v1 + bv.y) : 0.0f) + xr.y;
                    *(float2*)&out[n * CDIM + c] = make_float2(o0, o1);
                }
            }
        }
    }
}

// ============================================================
// Flash attention, cp.async double-buffered, pre-laid-out K/V.
// Grid (32 q-tiles, 8 heads), 256 threads = 8 warps x 16 q. 64 key-tiles.
// ============================================================
#define NTILES 64

__global__ __launch_bounds__(256) void flash_tc_kernel() {
    const int head = blockIdx.y;
    const int qt   = blockIdx.x * 128;
    const int tid  = threadIdx.x;
    const int warp = tid >> 5;
    const int lane = tid & 31;
    const int g8   = lane >> 2;
    const int tig  = lane & 3;

    __shared__ __align__(16) uint32_t Ks[2][64][36];
    __shared__ __align__(16) uint32_t Vt[2][2][32][34];
    __shared__ __align__(16) float mk[2][64];

    const float* Q = g_q + head * N_TOK * HD;
    const uint32_t* KF = g_kf + head * N_TOK * HD;
    const uint32_t* VT = g_vt + head * N_TOK * HD;

    // --- Q A-fragments (one-time), pre-scaled by scale*log2e ---
    const int qr0 = qt + warp * 16 + g8;
    const int qr1 = qr0 + 8;
    uint32_t qa[4][4];
    #pragma unroll
    for (int kc = 0; kc < 4; kc++) {
        int c0 = kc * 8 + tig;
        qa[kc][0] = f2tf(Q[qr0 * HD + c0]     * QSCALE);
        qa[kc][1] = f2tf(Q[qr1 * HD + c0]     * QSCALE);
        qa[kc][2] = f2tf(Q[qr0 * HD + c0 + 4] * QSCALE);
        qa[kc][3] = f2tf(Q[qr1 * HD + c0 + 4] * QSCALE);
    }

    float m0 = -1e30f, m1 = -1e30f, l0 = 0.0f, l1 = 0.0f;
    float o[4][4];
    #pragma unroll
    for (int nb = 0; nb < 4; nb++)
        #pragma unroll
        for (int j = 0; j < 4; j++) o[nb][j] = 0.0f;

    const int srcA = (lane & 28) | (tig >> 1);
    const int srcB = srcA + 2;
    const bool oddt = (tig & 1);

    // ---- prologue stage (buf 0, tile 0) ----
    {
        #pragma unroll
        for (int t = 0; t < 2; t++) {
            int c = tid + t * 256;
            int key = c >> 3, ch = (c & 7) * 4;
            cp16(&Ks[0][key][ch], KF + key * HD + ch);
        }
        #pragma unroll
        for (int t = 0; t < 4; t++) {
            int c = tid + t * 256;
            int hv = c >> 9, d = (c >> 4) & 31, pr = (c & 15) * 2;
            cp8(&Vt[0][hv][d][pr], VT + hv * 1024 + d * 32 + pr);
        }
        if (tid < 64) mk[0][tid] = g_kmask[tid];
        cp_commit();
    }

    for (int it = 0; it < NTILES; it++) {
        const int buf = it & 1;
        if (it + 1 < NTILES) {
            const int nb1 = buf ^ 1;
            const int ka = (it + 1) * 64;
            #pragma unroll
            for (int t = 0; t < 2; t++) {
                int c = tid + t * 256;
                int key = c >> 3, ch = (c & 7) * 4;
                cp16(&Ks[nb1][key][ch], KF + (ka + key) * HD + ch);
            }
            const uint32_t* vg = VT + (it + 1) * 2048;
            #pragma unroll
            for (int t = 0; t < 4; t++) {
                int c = tid + t * 256;
                int hv = c >> 9, d = (c >> 4) & 31, pr = (c & 15) * 2;
                cp8(&Vt[nb1][hv][d][pr], vg + hv * 1024 + d * 32 + pr);
            }
            if (tid < 64) mk[nb1][tid] = g_kmask[ka + tid];
            cp_commit();
            cp_wait1();
        } else {
            cp_wait0();
        }
        __syncthreads();

        // --- S = Q K^T ---
        float sc[8][4];
        #pragma unroll
        for (int nb = 0; nb < 8; nb++) {
            uint32_t kb[8];
            *(uint4*)&kb[0] = *(const uint4*)&Ks[buf][nb * 8 + g8][tig * 8];
            *(uint4*)&kb[4] = *(const uint4*)&Ks[buf][nb * 8 + g8][tig * 8 + 4];
            sc[nb][0] = sc[nb][1] = sc[nb][2] = sc[nb][3] = 0.0f;
            #pragma unroll
            for (int kc = 0; kc < 4; kc++)
                mma_tf32(sc[nb], qa[kc], kb[kc * 2], kb[kc * 2 + 1]);
            float ma = mk[buf][nb * 8 + 2 * tig];
            float mb = mk[buf][nb * 8 + 2 * tig + 1];
            sc[nb][0] += ma; sc[nb][1] += mb;
            sc[nb][2] += ma; sc[nb][3] += mb;
        }

        // --- online softmax ---
        float rm0 = -1e30f, rm1 = -1e30f;
        #pragma unroll
        for (int nb = 0; nb < 8; nb++) {
            rm0 = fmaxf(rm0, fmaxf(sc[nb][0], sc[nb][1]));
            rm1 = fmaxf(rm1, fmaxf(sc[nb][2], sc[nb][3]));
        }
        rm0 = fmaxf(rm0, __shfl_xor_sync(0xffffffffu, rm0, 1));
        rm0 = fmaxf(rm0, __shfl_xor_sync(0xffffffffu, rm0, 2));
        rm1 = fmaxf(rm1, __shfl_xor_sync(0xffffffffu, rm1, 1));
        rm1 = fmaxf(rm1, __shfl_xor_sync(0xffffffffu, rm1, 2));

        float mn0 = fmaxf(m0, rm0);
        float mn1 = fmaxf(m1, rm1);
        float corr0 = ex2(m0 - mn0);
        float corr1 = ex2(m1 - mn1);
        m0 = mn0; m1 = mn1;
        l0 *= corr0; l1 *= corr1;
        #pragma unroll
        for (int nb = 0; nb < 4; nb++) {
            o[nb][0] *= corr0; o[nb][1] *= corr0;
            o[nb][2] *= corr1; o[nb][3] *= corr1;
        }

        // --- P = 2^(S-m) ---
        uint32_t up[8][4];
        #pragma unroll
        for (int nb = 0; nb < 8; nb++) {
            float p0 = ex2(sc[nb][0] - mn0);
            float p1 = ex2(sc[nb][1] - mn0);
            float p2 = ex2(sc[nb][2] - mn1);
            float p3 = ex2(sc[nb][3] - mn1);
            l0 += p0 + p1;
            l1 += p2 + p3;
            up[nb][0] = f2tf(p0); up[nb][1] = f2tf(p1);
            up[nb][2] = f2tf(p2); up[nb][3] = f2tf(p3);
        }

        // --- O += P V ---
        #pragma unroll
        for (int kc = 0; kc < 8; kc++) {
            uint32_t s0 = __shfl_sync(0xffffffffu, up[kc][0], srcA);
            uint32_t s1 = __shfl_sync(0xffffffffu, up[kc][1], srcA);
            uint32_t s2 = __shfl_sync(0xffffffffu, up[kc][2], srcA);
            uint32_t s3 = __shfl_sync(0xffffffffu, up[kc][3], srcA);
            uint32_t t0 = __shfl_sync(0xffffffffu, up[kc][0], srcB);
            uint32_t t1 = __shfl_sync(0xffffffffu, up[kc][1], srcB);
            uint32_t t2 = __shfl_sync(0xffffffffu, up[kc][2], srcB);
            uint32_t t3 = __shfl_sync(0xffffffffu, up[kc][3], srcB);
            uint32_t pa[4];
            pa[0] = oddt ? s1 : s0;
            pa[1] = oddt ? s3 : s2;
            pa[2] = oddt ? t1 : t0;
            pa[3] = oddt ? t3 : t2;
            int hf = kc >> 2;
            int co = tig * 8 + ((kc & 3) << 1);
            #pragma unroll
            for (int nb = 0; nb < 4; nb++) {
                uint2 bv = *(const uint2*)&Vt[buf][hf][nb * 8 + g8][co];
                mma_tf32(o[nb], pa, bv.x, bv.y);
            }
        }
        __syncthreads();
    }

    // --- epilogue: normalize, write ---
    l0 += __shfl_xor_sync(0xffffffffu, l0, 1);
    l0 += __shfl_xor_sync(0xffffffffu, l0, 2);
    l1 += __shfl_xor_sync(0xffffffffu, l1, 1);
    l1 += __shfl_xor_sync(0xffffffffu, l1, 2);
    float inv0 = (l0 > 0.0f) ? (1.0f / l0) : 0.0f;
    float inv1 = (l1 > 0.0f) ? (1.0f / l1) : 0.0f;

    #pragma unroll
    for (int nb = 0; nb < 4; nb++) {
        int col = head * HD + nb * 8 + 2 * tig;
        *(float2*)&g_ao[qr0 * CDIM + col] = make_float2(o[nb][0] * inv0, o[nb][1] * inv0);
        *(float2*)&g_ao[qr1 * CDIM + col] = make_float2(o[nb][2] * inv1, o[nb][3] * inv1);
    }
}

// ============================================================
extern "C" void kernel_launch(void* const* d_in, const int* in_sizes, int n_in,
                              void* d_out, int out_size) {
    const float* x      = (const float*)d_in[0];
    const float* dbz    = (const float*)d_in[1];
    const float* qkv_w  = (const float*)d_in[2];
    const float* proj_w = (const float*)d_in[3];
    const float* proj_b = (const float*)d_in[4];
    float* out = (float*)d_out;

    keep_kernel<<<16, 256>>>(dbz);
    gemm_tc<0><<<dim3(768 / 64, N_TOK / 128), 256>>>(x, qkv_w, nullptr, nullptr, nullptr);
    flash_tc_kernel<<<dim3(N_TOK / 128, NH), 256>>>();
    gemm_tc<1><<<dim3(CDIM / 64, N_TOK / 128), 256>>>(nullptr, proj_w, proj_b, x, out);
}

// round 11
// speedup vs baseline: 2.8371x; 1.8120x over previous
#include <cuda_runtime.h>
#include <cuda_fp16.h>
#include <math.h>
#include <stdint.h>

#define N_TOK 4096
#define CDIM 256
#define NH 8
#define HD 32
#define QSCALE (0.17677669529663687f * 1.4426950408889634f)  // 32^-0.5 * log2(e)

// ---- scratch (device globals) ----
__device__ uint32_t g_qh[NH * N_TOK * 16];   // fp16x2 pairs (d,d+1), scaled, [head][n][p]
__device__ uint32_t g_kh[NH * N_TOK * 16];   // fp16x2 pairs (d,d+1), B-frag perm, [head][key][pos]
__device__ uint32_t g_vh[NH * 2048 * 32];    // fp16x2 pairs (key,key+1), [head][j][pos]
__device__ float    g_ao[N_TOK * CDIM];
__device__ float    g_kmask[N_TOK];          // 0.f kept, -1e30f dropped

// ============================================================
__device__ __forceinline__ uint32_t f2tf(float f) {
    uint32_t r; asm("cvt.rna.tf32.f32 %0, %1;" : "=r"(r) : "f"(f)); return r;
}
__device__ __forceinline__ float ex2(float x) {
    float r; asm("ex2.approx.ftz.f32 %0, %1;" : "=f"(r) : "f"(x)); return r;
}
__device__ __forceinline__ uint32_t packh2(float lo, float hi) {
    __half2 h = __floats2half2_rn(lo, hi);
    return *(uint32_t*)&h;
}
__device__ __forceinline__ void mma_tf32(float c[4], const uint32_t a[4],
                                         uint32_t b0, uint32_t b1) {
    asm volatile(
        "mma.sync.aligned.m16n8k8.row.col.f32.tf32.tf32.f32 "
        "{%0,%1,%2,%3},{%4,%5,%6,%7},{%8,%9},{%0,%1,%2,%3};"
        : "+f"(c[0]), "+f"(c[1]), "+f"(c[2]), "+f"(c[3])
        : "r"(a[0]), "r"(a[1]), "r"(a[2]), "r"(a[3]), "r"(b0), "r"(b1));
}
__device__ __forceinline__ void mma_f16(float c[4], const uint32_t a[4],
                                        uint32_t b0, uint32_t b1) {
    asm volatile(
        "mma.sync.aligned.m16n8k16.row.col.f32.f16.f16.f32 "
        "{%0,%1,%2,%3},{%4,%5,%6,%7},{%8,%9},{%0,%1,%2,%3};"
        : "+f"(c[0]), "+f"(c[1]), "+f"(c[2]), "+f"(c[3])
        : "r"(a[0]), "r"(a[1]), "r"(a[2]), "r"(a[3]), "r"(b0), "r"(b1));
}
__device__ __forceinline__ void cp16(void* s, const void* g) {
    uint32_t sa = (uint32_t)__cvta_generic_to_shared(s);
    asm volatile("cp.async.cg.shared.global [%0], [%1], 16;\n" :: "r"(sa), "l"(g) : "memory");
}
__device__ __forceinline__ void cp_commit() { asm volatile("cp.async.commit_group;\n" ::: "memory"); }
__device__ __forceinline__ void cp_wait1()  { asm volatile("cp.async.wait_group 1;\n" ::: "memory"); }
__device__ __forceinline__ void cp_wait0()  { asm volatile("cp.async.wait_group 0;\n" ::: "memory"); }

// ============================================================
// Keep mask: keep = 3x3 dilation of (dbz >= 15)
// ============================================================
__global__ void keep_kernel(const float* __restrict__ dbz) {
    int n = blockIdx.x * 256 + threadIdx.x;
    if (n >= N_TOK) return;
    int t   = n >> 10;
    int rem = n & 1023;
    int y   = rem >> 5;
    int x   = rem & 31;
    const float* d = dbz + t * 1024;
    bool k = false;
    #pragma unroll
    for (int dy = -1; dy <= 1; dy++) {
        int yy = y + dy;
        if (yy < 0 || yy >= 32) continue;
        #pragma unroll
        for (int dx = -1; dx <= 1; dx++) {
            int xx = x + dx;
            if (xx < 0 || xx >= 32) continue;
            k = k || (d[yy * 32 + xx] >= 15.0f);
        }
    }
    g_kmask[n] = k ? 0.0f : -1e30f;
}

// ============================================================
// Tensor-core tf32 GEMM with register prefetch: C = A[M,256] * B[N,256]^T
// CTA tile 128x64, BK=32, 8 warps. MODE 0: qkv -> fp16 q/k/v layouts.
// MODE 1: proj epilogue.
// ============================================================
template <int MODE>
__global__ __launch_bounds__(256) void gemm_tc(
    const float* __restrict__ A, const float* __restrict__ B,
    const float* __restrict__ bias, const float* __restrict__ xres,
    float* __restrict__ out)
{
    __shared__ __align__(16) uint32_t As[128][36];
    __shared__ __align__(16) uint32_t Bs[64][36];

    const float* Ap = (MODE == 0) ? A : g_ao;

    const int tid  = threadIdx.x;
    const int warp = tid >> 5;
    const int lane = tid & 31;
    const int grp  = lane >> 2;
    const int tig  = lane & 3;
    const int wm   = warp >> 1;
    const int wn   = warp & 1;
    const int row0 = blockIdx.y * 128;
    const int col0 = blockIdx.x * 64;

    const int lr = tid >> 3;          // 0..31 base row unit
    const int lk = tid & 7;           // k-quad
    const int cb = ((lk >> 1) << 1) | (lk & 1);

    float acc[2][4][4];
    #pragma unroll
    for (int mi = 0; mi < 2; mi++)
        #pragma unroll
        for (int ni = 0; ni < 4; ni++)
            #pragma unroll
            for (int j = 0; j < 4; j++) acc[mi][ni][j] = 0.0f;

    // register prefetch buffers
    float4 pva[4], pvb[2];
    #pragma unroll
    for (int t = 0; t < 4; t++)
        pva[t] = *(const float4*)&Ap[(row0 + lr + t * 32) * CDIM + lk * 4];
    #pragma unroll
    for (int t = 0; t < 2; t++)
        pvb[t] = *(const float4*)&B[(col0 + lr + t * 32) * CDIM + lk * 4];

    for (int k0 = 0; k0 < CDIM; k0 += 32) {
        __syncthreads();
        #pragma unroll
        for (int t = 0; t < 4; t++) {
            int r = lr + t * 32;
            As[r][cb]      = f2tf(pva[t].x);
            As[r][cb + 8]  = f2tf(pva[t].y);
            As[r][cb + 16] = f2tf(pva[t].z);
            As[r][cb + 24] = f2tf(pva[t].w);
        }
        #pragma unroll
        for (int t = 0; t < 2; t++) {
            int r = lr + t * 32;
            Bs[r][cb]      = f2tf(pvb[t].x);
            Bs[r][cb + 8]  = f2tf(pvb[t].y);
            Bs[r][cb + 16] = f2tf(pvb[t].z);
            Bs[r][cb + 24] = f2tf(pvb[t].w);
        }
        __syncthreads();

        if (k0 + 32 < CDIM) {
            #pragma unroll
            for (int t = 0; t < 4; t++)
                pva[t] = *(const float4*)&Ap[(row0 + lr + t * 32) * CDIM + k0 + 32 + lk * 4];
            #pragma unroll
            for (int t = 0; t < 2; t++)
                pvb[t] = *(const float4*)&B[(col0 + lr + t * 32) * CDIM + k0 + 32 + lk * 4];
        }

        uint32_t alo[2][8], ahi[2][8], bb[4][8];
        #pragma unroll
        for (int mi = 0; mi < 2; mi++) {
            int r = wm * 32 + mi * 16 + grp;
            *(uint4*)&alo[mi][0] = *(const uint4*)&As[r][tig * 8];
            *(uint4*)&alo[mi][4] = *(const uint4*)&As[r][tig * 8 + 4];
            *(uint4*)&ahi[mi][0] = *(const uint4*)&As[r + 8][tig * 8];
            *(uint4*)&ahi[mi][4] = *(const uint4*)&As[r + 8][tig * 8 + 4];
        }
        #pragma unroll
        for (int ni = 0; ni < 4; ni++) {
            int c = wn * 32 + ni * 8 + grp;
            *(uint4*)&bb[ni][0] = *(const uint4*)&Bs[c][tig * 8];
            *(uint4*)&bb[ni][4] = *(const uint4*)&Bs[c][tig * 8 + 4];
        }
        #pragma unroll
        for (int kc = 0; kc < 4; kc++)
            #pragma unroll
            for (int mi = 0; mi < 2; mi++) {
                uint32_t a[4] = {alo[mi][kc * 2], ahi[mi][kc * 2],
                                 alo[mi][kc * 2 + 1], ahi[mi][kc * 2 + 1]};
                #pragma unroll
                for (int ni = 0; ni < 4; ni++)
                    mma_tf32(acc[mi][ni], a, bb[ni][kc * 2], bb[ni][kc * 2 + 1]);
            }
    }

    #pragma unroll
    for (int mi = 0; mi < 2; mi++) {
        int rA = row0 + wm * 32 + mi * 16 + grp;
        #pragma unroll
        for (int half = 0; half < 2; half++) {
            int n = rA + half * 8;
            #pragma unroll
            for (int ni = 0; ni < 4; ni++) {
                int c = col0 + wn * 32 + ni * 8 + 2 * tig;
                float v0 = acc[mi][ni][half * 2 + 0];
                float v1 = acc[mi][ni][half * 2 + 1];
                if (MODE == 0) {
                    int part = c >> 8;
                    int cc   = c & 255;
                    int hh   = cc >> 5;
                    int dd   = cc & 31;       // even
                    if (part == 0) {
                        // Q: fp16 pair (d,d+1), pre-scaled
                        g_qh[(hh * N_TOK + n) * 16 + (dd >> 1)] =
                            packh2(v0 * QSCALE, v1 * QSCALE);
                    } else if (part == 1) {
                        // K: fp16 pair, permuted pos = (p&3)*4 + (p>>2)
                        int p = dd >> 1;
                        int pos = ((p & 3) << 2) | (p >> 2);
                        g_kh[(hh * N_TOK + n) * 16 + pos] = packh2(v0, v1);
                    } else {
                        // V: scalar halves, pair across keys; pos = (d&7)*4 + (d>>3)
                        int j   = n >> 1;
                        int par = n & 1;
                        int pos0 = ((dd & 7) << 2) | (dd >> 3);
                        int dd1  = dd + 1;
                        int pos1 = ((dd1 & 7) << 2) | (dd1 >> 3);
                        uint16_t* vp = (uint16_t*)g_vh;
                        int base = (hh * 2048 + j) * 32;
                        __half h0 = __float2half_rn(v0);
                        __half h1 = __float2half_rn(v1);
                        vp[(base + pos0) * 2 + par] = *(uint16_t*)&h0;
                        vp[(base + pos1) * 2 + par] = *(uint16_t*)&h1;
                    }
                } else {
                    bool keep = (g_kmask[n] == 0.0f);
                    float2 bv = *(const float2*)&bias[c];
                    float2 xr = *(const float2*)&xres[n * CDIM + c];
                    float o0 = (keep ? (v0 + bv.x) : 0.0f) + xr.x;
                    float o1 = (keep ? (v1 + bv.y) : 0.0f) + xr.y;
                    *(float2*)&out[n * CDIM + c] = make_float2(o0, o1);
                }
            }
        }
    }
}

// ============================================================
// Flash attention, fp16 m16n8k16, zero-shuffle P reuse,
// cp.async double-buffered. Grid (32, 8), 256 threads.
// ============================================================
#define NTILES 64

__global__ __launch_bounds__(256) void flash_tc_kernel() {
    const int head = blockIdx.y;
    const int qt   = blockIdx.x * 128;
    const int tid  = threadIdx.x;
    const int warp = tid >> 5;
    const int lane = tid & 31;
    const int g8   = lane >> 2;
    const int tig  = lane & 3;

    __shared__ __align__(16) uint32_t Kh[2][64][16];   // 4KB/buf
    __shared__ __align__(16) uint32_t Vh[2][32][40];   // 5KB/buf (stride 40: conflict-free)
    __shared__ __align__(16) float mk[2][64];

    const uint32_t* QH = g_qh + head * N_TOK * 16;
    const uint32_t* KH = g_kh + head * N_TOK * 16;
    const uint32_t* VH = g_vh + head * 2048 * 32;

    // --- Q A-fragments (fp16, pre-scaled, one-time) ---
    const int qr0 = qt + warp * 16 + g8;
    const int qr1 = qr0 + 8;
    uint32_t qa[2][4];
    #pragma unroll
    for (int kc = 0; kc < 2; kc++) {
        qa[kc][0] = QH[qr0 * 16 + kc * 8 + tig];
        qa[kc][1] = QH[qr1 * 16 + kc * 8 + tig];
        qa[kc][2] = QH[qr0 * 16 + kc * 8 + tig + 4];
        qa[kc][3] = QH[qr1 * 16 + kc * 8 + tig + 4];
    }

    float m0 = -1e30f, m1 = -1e30f, l0 = 0.0f, l1 = 0.0f;
    float o[4][4];
    #pragma unroll
    for (int nb = 0; nb < 4; nb++)
        #pragma unroll
        for (int j = 0; j < 4; j++) o[nb][j] = 0.0f;

    // ---- prologue stage (buf 0, tile 0): 1 cp16 each for K and V ----
    {
        int c = tid;
        cp16(&Kh[0][c >> 2][(c & 3) * 4], KH + (c >> 2) * 16 + (c & 3) * 4);
        cp16(&Vh[0][c >> 3][(c & 7) * 4], VH + (c >> 3) * 32 + (c & 7) * 4);
        if (tid < 64) mk[0][tid] = g_kmask[tid];
        cp_commit();
    }

    for (int it = 0; it < NTILES; it++) {
        const int buf = it & 1;
        if (it + 1 < NTILES) {
            const int nb1 = buf ^ 1;
            const int ka = (it + 1) * 64;
            int c = tid;
            cp16(&Kh[nb1][c >> 2][(c & 3) * 4], KH + (ka + (c >> 2)) * 16 + (c & 3) * 4);
            cp16(&Vh[nb1][c >> 3][(c & 7) * 4],
                 VH + ((it + 1) * 32 + (c >> 3)) * 32 + (c & 7) * 4);
            if (tid < 64) mk[nb1][tid] = g_kmask[ka + tid];
            cp_commit();
            cp_wait1();
        } else {
            cp_wait0();
        }
        __syncthreads();

        // --- S = Q K^T  (8 key-blocks, fp16 k16: 2 MMA + 1 LDS.128 each) ---
        float sc[8][4];
        #pragma unroll
        for (int nbk = 0; nbk < 8; nbk++) {
            uint32_t kb[4];
            *(uint4*)kb = *(const uint4*)&Kh[buf][nbk * 8 + g8][tig * 4];
            sc[nbk][0] = sc[nbk][1] = sc[nbk][2] = sc[nbk][3] = 0.0f;
            mma_f16(sc[nbk], qa[0], kb[0], kb[1]);
            mma_f16(sc[nbk], qa[1], kb[2], kb[3]);
            float ma = mk[buf][nbk * 8 + 2 * tig];
            float mb = mk[buf][nbk * 8 + 2 * tig + 1];
            sc[nbk][0] += ma; sc[nbk][1] += mb;
            sc[nbk][2] += ma; sc[nbk][3] += mb;
        }

        // --- online softmax (log2 domain) ---
        float rm0 = -1e30f, rm1 = -1e30f;
        #pragma unroll
        for (int nb = 0; nb < 8; nb++) {
            rm0 = fmaxf(rm0, fmaxf(sc[nb][0], sc[nb][1]));
            rm1 = fmaxf(rm1, fmaxf(sc[nb][2], sc[nb][3]));
        }
        rm0 = fmaxf(rm0, __shfl_xor_sync(0xffffffffu, rm0, 1));
        rm0 = fmaxf(rm0, __shfl_xor_sync(0xffffffffu, rm0, 2));
        rm1 = fmaxf(rm1, __shfl_xor_sync(0xffffffffu, rm1, 1));
        rm1 = fmaxf(rm1, __shfl_xor_sync(0xffffffffu, rm1, 2));

        float mn0 = fmaxf(m0, rm0);
        float mn1 = fmaxf(m1, rm1);
        float corr0 = ex2(m0 - mn0);
        float corr1 = ex2(m1 - mn1);
        m0 = mn0; m1 = mn1;
        l0 *= corr0; l1 *= corr1;
        #pragma unroll
        for (int nb = 0; nb < 4; nb++) {
            o[nb][0] *= corr0; o[nb][1] *= corr0;
            o[nb][2] *= corr1; o[nb][3] *= corr1;
        }

        // --- P = 2^(S-m), in place ---
        #pragma unroll
        for (int nb = 0; nb < 8; nb++) {
            float p0 = ex2(sc[nb][0] - mn0);
            float p1 = ex2(sc[nb][1] - mn0);
            float p2 = ex2(sc[nb][2] - mn1);
            float p3 = ex2(sc[nb][3] - mn1);
            l0 += p0 + p1;
            l1 += p2 + p3;
            sc[nb][0] = p0; sc[nb][1] = p1;
            sc[nb][2] = p2; sc[nb][3] = p3;
        }

        // --- O += P V : C-frag == A-frag after f16x2 pack (no shuffles) ---
        #pragma unroll
        for (int kcc = 0; kcc < 4; kcc++) {
            uint32_t pa[4];
            pa[0] = packh2(sc[2 * kcc][0],     sc[2 * kcc][1]);
            pa[1] = packh2(sc[2 * kcc][2],     sc[2 * kcc][3]);
            pa[2] = packh2(sc[2 * kcc + 1][0], sc[2 * kcc + 1][1]);
            pa[3] = packh2(sc[2 * kcc + 1][2], sc[2 * kcc + 1][3]);
            uint32_t vb0[4], vb1[4];
            *(uint4*)vb0 = *(const uint4*)&Vh[buf][kcc * 8 + tig][g8 * 4];
            *(uint4*)vb1 = *(const uint4*)&Vh[buf][kcc * 8 + tig + 4][g8 * 4];
            #pragma unroll
            for (int nb = 0; nb < 4; nb++)
                mma_f16(o[nb], pa, vb0[nb], vb1[nb]);
        }
        __syncthreads();
    }

    // --- epilogue: normalize, write ---
    l0 += __shfl_xor_sync(0xffffffffu, l0, 1);
    l0 += __shfl_xor_sync(0xffffffffu, l0, 2);
    l1 += __shfl_xor_sync(0xffffffffu, l1, 1);
    l1 += __shfl_xor_sync(0xffffffffu, l1, 2);
    float inv0 = (l0 > 0.0f) ? (1.0f / l0) : 0.0f;
    float inv1 = (l1 > 0.0f) ? (1.0f / l1) : 0.0f;

    #pragma unroll
    for (int nb = 0; nb < 4; nb++) {
        int col = head * HD + nb * 8 + 2 * tig;
        *(float2*)&g_ao[qr0 * CDIM + col] = make_float2(o[nb][0] * inv0, o[nb][1] * inv0);
        *(float2*)&g_ao[qr1 * CDIM + col] = make_float2(o[nb][2] * inv1, o[nb][3] * inv1);
    }
}

// ============================================================
extern "C" void kernel_launch(void* const* d_in, const int* in_sizes, int n_in,
                              void* d_out, int out_size) {
    const float* x      = (const float*)d_in[0];
    const float* dbz    = (const float*)d_in[1];
    const float* qkv_w  = (const float*)d_in[2];
    const float* proj_w = (const float*)d_in[3];
    const float* proj_b = (const float*)d_in[4];
    float* out = (float*)d_out;

    keep_kernel<<<16, 256>>>(dbz);
    gemm_tc<0><<<dim3(768 / 64, N_TOK / 128), 256>>>(x, qkv_w, nullptr, nullptr, nullptr);
    flash_tc_kernel<<<dim3(N_TOK / 128, NH), 256>>>();
    gemm_tc<1><<<dim3(CDIM / 64, N_TOK / 128), 256>>>(nullptr, proj_w, proj_b, x, out);
}

// round 13
// speedup vs baseline: 3.1413x; 1.1072x over previous
#include <cuda_runtime.h>
#include <cuda_fp16.h>
#include <math.h>
#include <stdint.h>

#define N_TOK 4096
#define CDIM 256
#define NH 8
#define HD 32
#define QSCALE (0.17677669529663687f * 1.4426950408889634f)  // 32^-0.5 * log2(e)

// ---- scratch (device globals) ----
__device__ uint32_t g_xh [N_TOK * 128];      // x as fp16x2, frag-permuted rows of 128 u32
__device__ uint32_t g_qwh[768 * 128];        // qkv_w fp16x2 permuted
__device__ uint32_t g_pwh[CDIM * 128];       // proj_w fp16x2 permuted
__device__ uint32_t g_ah [N_TOK * 128];      // attention out fp16x2 permuted (proj A)
__device__ uint32_t g_qh [NH * N_TOK * 16];  // Q fp16x2 pairs, scaled, plain p order
__device__ uint32_t g_kh [NH * N_TOK * 16];  // K fp16x2, B-frag perm
__device__ uint32_t g_vh [NH * 2048 * 32];   // V fp16x2 pairs across keys
__device__ float    g_kmask[N_TOK];          // 0.f kept, -1e30f dropped

#define XW (N_TOK * 128)
#define QW (768 * 128)
#define PW (CDIM * 128)

// ============================================================
__device__ __forceinline__ float ex2(float x) {
    float r; asm("ex2.approx.ftz.f32 %0, %1;" : "=f"(r) : "f"(x)); return r;
}
__device__ __forceinline__ uint32_t packh2(float lo, float hi) {
    __half2 h = __floats2half2_rn(lo, hi);
    return *(uint32_t*)&h;
}
__device__ __forceinline__ void mma_f16(float c[4], const uint32_t a[4],
                                        uint32_t b0, uint32_t b1) {
    asm volatile(
        "mma.sync.aligned.m16n8k16.row.col.f32.f16.f16.f32 "
        "{%0,%1,%2,%3},{%4,%5,%6,%7},{%8,%9},{%0,%1,%2,%3};"
        : "+f"(c[0]), "+f"(c[1]), "+f"(c[2]), "+f"(c[3])
        : "r"(a[0]), "r"(a[1]), "r"(a[2]), "r"(a[3]), "r"(b0), "r"(b1));
}
__device__ __forceinline__ void cp16(void* s, const void* g) {
    uint32_t sa = (uint32_t)__cvta_generic_to_shared(s);
    asm volatile("cp.async.cg.shared.global [%0], [%1], 16;\n" :: "r"(sa), "l"(g) : "memory");
}
__device__ __forceinline__ void cp_commit() { asm volatile("cp.async.commit_group;\n" ::: "memory"); }
__device__ __forceinline__ void cp_wait1()  { asm volatile("cp.async.wait_group 1;\n" ::: "memory"); }
__device__ __forceinline__ void cp_wait0()  { asm volatile("cp.async.wait_group 0;\n" ::: "memory"); }

// ============================================================
// Prep: fp16-convert + fragment-permute x/qkv_w/proj_w, plus keep mask.
// pos within each 16-u32 (32-k) group: p -> 4*(p&3) + (p>>2)
// ============================================================
__global__ __launch_bounds__(256) void prep_kernel(
    const float* __restrict__ x, const float* __restrict__ dbz,
    const float* __restrict__ qkv_w, const float* __restrict__ proj_w)
{
    int idx = blockIdx.x * 256 + threadIdx.x;
    if (idx < XW + QW + PW) {
        const float* src; uint32_t* dst; int rel;
        if (idx < XW)           { src = x;      dst = g_xh;  rel = idx; }
        else if (idx < XW + QW) { src = qkv_w;  dst = g_qwh; rel = idx - XW; }
        else                    { src = proj_w; dst = g_pwh; rel = idx - XW - QW; }
        int row = rel >> 7, p = rel & 127;
        int gk = p >> 4, q = p & 15;
        int pos = (gk << 4) | ((q & 3) << 2) | (q >> 2);
        float2 v = *(const float2*)&src[row * 256 + p * 2];
        dst[(row << 7) + pos] = packh2(v.x, v.y);
    } else {
        int n = idx - (XW + QW + PW);
        if (n < N_TOK) {
            int t = n >> 10, rem = n & 1023, y = rem >> 5, xx0 = rem & 31;
            const float* d = dbz + t * 1024;
            bool k = false;
            #pragma unroll
            for (int dy = -1; dy <= 1; dy++) {
                int yy = y + dy;
                if (yy < 0 || yy >= 32) continue;
                #pragma unroll
                for (int dx = -1; dx <= 1; dx++) {
                    int xx = xx0 + dx;
                    if (xx < 0 || xx >= 32) continue;
                    k = k || (d[yy * 32 + xx] >= 15.0f);
                }
            }
            g_kmask[n] = k ? 0.0f : -1e30f;
        }
    }
}

// ============================================================
// fp16 tensor-core GEMM: C[M,N] = A[M,256] * B[N,256]^T
// CTA tile 128x64, BK=32, cp.async double-buffered, 8 warps (4x2).
// MODE 0: A=g_xh, B=g_qwh -> scatter fp16 q/k/v flash layouts.
// MODE 1: A=g_ah, B=g_pwh -> bias + querymask + residual epilogue.
// ============================================================
template <int MODE>
__global__ __launch_bounds__(256) void gemm_h(
    const float* __restrict__ bias, const float* __restrict__ xres,
    float* __restrict__ out)
{
    __shared__ __align__(16) uint32_t As[2][128][16];
    __shared__ __align__(16) uint32_t Bs[2][64][16];

    const uint32_t* Ag = (MODE == 0) ? g_xh : g_ah;
    const uint32_t* Bg = (MODE == 0) ? g_qwh : g_pwh;

    const int tid  = threadIdx.x;
    const int warp = tid >> 5;
    const int lane = tid & 31;
    const int grp  = lane >> 2;
    const int tig  = lane & 3;
    const int wm   = warp >> 1;
    const int wn   = warp & 1;
    const int row0 = blockIdx.y * 128;
    const int col0 = blockIdx.x * 64;

    float acc[2][4][4];
    #pragma unroll
    for (int mi = 0; mi < 2; mi++)
        #pragma unroll
        for (int ni = 0; ni < 4; ni++)
            #pragma unroll
            for (int j = 0; j < 4; j++) acc[mi][ni][j] = 0.0f;

    // ---- prologue stage (buf 0, k0=0) ----
    {
        #pragma unroll
        for (int t = 0; t < 2; t++) {
            int i = tid + t * 256;
            int r = i >> 2, c = i & 3;
            cp16(&As[0][r][c * 4], Ag + (row0 + r) * 128 + c * 4);
        }
        int r = tid >> 2, c = tid & 3;
        cp16(&Bs[0][r][c * 4], Bg + (col0 + r) * 128 + c * 4);
        cp_commit();
    }

    #pragma unroll
    for (int it = 0; it < 8; it++) {
        const int buf = it & 1;
        if (it + 1 < 8) {
            const int nb1 = buf ^ 1;
            const int kw = (it + 1) * 16;
            #pragma unroll
            for (int t = 0; t < 2; t++) {
                int i = tid + t * 256;
                int r = i >> 2, c = i & 3;
                cp16(&As[nb1][r][c * 4], Ag + (row0 + r) * 128 + kw + c * 4);
            }
            int r = tid >> 2, c = tid & 3;
            cp16(&Bs[nb1][r][c * 4], Bg + (col0 + r) * 128 + kw + c * 4);
            cp_commit();
            cp_wait1();
        } else {
            cp_wait0();
        }
        __syncthreads();

        uint32_t wa[2][2][4], wb[4][4];
        #pragma unroll
        for (int mi = 0; mi < 2; mi++) {
            int r = wm * 32 + mi * 16 + grp;
            *(uint4*)wa[mi][0] = *(const uint4*)&As[buf][r][tig * 4];
            *(uint4*)wa[mi][1] = *(const uint4*)&As[buf][r + 8][tig * 4];
        }
        #pragma unroll
        for (int ni = 0; ni < 4; ni++) {
            int rb = wn * 32 + ni * 8 + grp;
            *(uint4*)wb[ni] = *(const uint4*)&Bs[buf][rb][tig * 4];
        }
        #pragma unroll
        for (int c = 0; c < 2; c++)
            #pragma unroll
            for (int mi = 0; mi < 2; mi++) {
                uint32_t a[4] = {wa[mi][0][c * 2], wa[mi][1][c * 2],
                                 wa[mi][0][c * 2 + 1], wa[mi][1][c * 2 + 1]};
                #pragma unroll
                for (int ni = 0; ni < 4; ni++)
                    mma_f16(acc[mi][ni], a, wb[ni][c * 2], wb[ni][c * 2 + 1]);
            }
        __syncthreads();
    }

    // ---- epilogue ----
    #pragma unroll
    for (int mi = 0; mi < 2; mi++) {
        int rA = row0 + wm * 32 + mi * 16 + grp;
        #pragma unroll
        for (int half = 0; half < 2; half++) {
            int n = rA + half * 8;
            #pragma unroll
            for (int ni = 0; ni < 4; ni++) {
                int c = col0 + wn * 32 + ni * 8 + 2 * tig;
                float v0 = acc[mi][ni][half * 2 + 0];
                float v1 = acc[mi][ni][half * 2 + 1];
                if (MODE == 0) {
                    int part = c >> 8;
                    int cc   = c & 255;
                    int hh   = cc >> 5;
                    int dd   = cc & 31;       // even
                    if (part == 0) {
                        g_qh[(hh * N_TOK + n) * 16 + (dd >> 1)] =
                            packh2(v0 * QSCALE, v1 * QSCALE);
                    } else if (part == 1) {
                        int p = dd >> 1;
                        int pos = ((p & 3) << 2) | (p >> 2);
                        g_kh[(hh * N_TOK + n) * 16 + pos] = packh2(v0, v1);
                    } else {
                        int j   = n >> 1;
                        int par = n & 1;
                        int pos0 = ((dd & 7) << 2) | (dd >> 3);
                        int dd1  = dd + 1;
                        int pos1 = ((dd1 & 7) << 2) | (dd1 >> 3);
                        uint16_t* vp = (uint16_t*)g_vh;
                        int base = (hh * 2048 + j) * 32;
                        __half h0 = __float2half_rn(v0);
                        __half h1 = __float2half_rn(v1);
                        vp[(base + pos0) * 2 + par] = *(uint16_t*)&h0;
                        vp[(base + pos1) * 2 + par] = *(uint16_t*)&h1;
                    }
                } else {
                    bool keep = (g_kmask[n] == 0.0f);
                    float2 bv = *(const float2*)&bias[c];
                    float2 xr = *(const float2*)&xres[n * CDIM + c];
                    float o0 = (keep ? (v0 + bv.x) : 0.0f) + xr.x;
                    float o1 = (keep ? (v1 + bv.y) : 0.0f) + xr.y;
                    *(float2*)&out[n * CDIM + c] = make_float2(o0, o1);
                }
            }
        }
    }
}

// ============================================================
// Flash attention, fp16 m16n8k16, zero-shuffle P reuse,
// cp.async double-buffered. Grid (32, 8), 256 threads.
// ============================================================
#define NTILES 64

__global__ __launch_bounds__(256) void flash_tc_kernel() {
    const int head = blockIdx.y;
    const int qt   = blockIdx.x * 128;
    const int tid  = threadIdx.x;
    const int warp = tid >> 5;
    const int lane = tid & 31;
    const int g8   = lane >> 2;
    const int tig  = lane & 3;

    __shared__ __align__(16) uint32_t Kh[2][64][16];   // 4KB/buf
    __shared__ __align__(16) uint32_t Vh[2][32][40];   // 5KB/buf
    __shared__ __align__(16) float mk[2][64];

    const uint32_t* QH = g_qh + head * N_TOK * 16;
    const uint32_t* KH = g_kh + head * N_TOK * 16;
    const uint32_t* VH = g_vh + head * 2048 * 32;

    // --- Q A-fragments (fp16, pre-scaled, one-time) ---
    const int qr0 = qt + warp * 16 + g8;
    const int qr1 = qr0 + 8;
    uint32_t qa[2][4];
    #pragma unroll
    for (int kc = 0; kc < 2; kc++) {
        qa[kc][0] = QH[qr0 * 16 + kc * 8 + tig];
        qa[kc][1] = QH[qr1 * 16 + kc * 8 + tig];
        qa[kc][2] = QH[qr0 * 16 + kc * 8 + tig + 4];
        qa[kc][3] = QH[qr1 * 16 + kc * 8 + tig + 4];
    }

    float m0 = -1e30f, m1 = -1e30f, l0 = 0.0f, l1 = 0.0f;
    float o[4][4];
    #pragma unroll
    for (int nb = 0; nb < 4; nb++)
        #pragma unroll
        for (int j = 0; j < 4; j++) o[nb][j] = 0.0f;

    // ---- prologue stage (buf 0, tile 0) ----
    {
        int c = tid;
        cp16(&Kh[0][c >> 2][(c & 3) * 4], KH + (c >> 2) * 16 + (c & 3) * 4);
        cp16(&Vh[0][c >> 3][(c & 7) * 4], VH + (c >> 3) * 32 + (c & 7) * 4);
        if (tid < 64) mk[0][tid] = g_kmask[tid];
        cp_commit();
    }

    for (int it = 0; it < NTILES; it++) {
        const int buf = it & 1;
        if (it + 1 < NTILES) {
            const int nb1 = buf ^ 1;
            const int ka = (it + 1) * 64;
            int c = tid;
            cp16(&Kh[nb1][c >> 2][(c & 3) * 4], KH + (ka + (c >> 2)) * 16 + (c & 3) * 4);
            cp16(&Vh[nb1][c >> 3][(c & 7) * 4],
                 VH + ((it + 1) * 32 + (c >> 3)) * 32 + (c & 7) * 4);
            if (tid < 64) mk[nb1][tid] = g_kmask[ka + tid];
            cp_commit();
            cp_wait1();
        } else {
            cp_wait0();
        }
        __syncthreads();

        // --- S = Q K^T ---
        float sc[8][4];
        #pragma unroll
        for (int nbk = 0; nbk < 8; nbk++) {
            uint32_t kb[4];
            *(uint4*)kb = *(const uint4*)&Kh[buf][nbk * 8 + g8][tig * 4];
            sc[nbk][0] = sc[nbk][1] = sc[nbk][2] = sc[nbk][3] = 0.0f;
            mma_f16(sc[nbk], qa[0], kb[0], kb[1]);
            mma_f16(sc[nbk], qa[1], kb[2], kb[3]);
            float ma = mk[buf][nbk * 8 + 2 * tig];
            float mb = mk[buf][nbk * 8 + 2 * tig + 1];
            sc[nbk][0] += ma; sc[nbk][1] += mb;
            sc[nbk][2] += ma; sc[nbk][3] += mb;
        }

        // --- online softmax (log2 domain) ---
        float rm0 = -1e30f, rm1 = -1e30f;
        #pragma unroll
        for (int nb = 0; nb < 8; nb++) {
            rm0 = fmaxf(rm0, fmaxf(sc[nb][0], sc[nb][1]));
            rm1 = fmaxf(rm1, fmaxf(sc[nb][2], sc[nb][3]));
        }
        rm0 = fmaxf(rm0, __shfl_xor_sync(0xffffffffu, rm0, 1));
        rm0 = fmaxf(rm0, __shfl_xor_sync(0xffffffffu, rm0, 2));
        rm1 = fmaxf(rm1, __shfl_xor_sync(0xffffffffu, rm1, 1));
        rm1 = fmaxf(rm1, __shfl_xor_sync(0xffffffffu, rm1, 2));

        float mn0 = fmaxf(m0, rm0);
        float mn1 = fmaxf(m1, rm1);
        float corr0 = ex2(m0 - mn0);
        float corr1 = ex2(m1 - mn1);
        m0 = mn0; m1 = mn1;
        l0 *= corr0; l1 *= corr1;
        #pragma unroll
        for (int nb = 0; nb < 4; nb++) {
            o[nb][0] *= corr0; o[nb][1] *= corr0;
            o[nb][2] *= corr1; o[nb][3] *= corr1;
        }

        // --- P = 2^(S-m), in place ---
        #pragma unroll
        for (int nb = 0; nb < 8; nb++) {
            float p0 = ex2(sc[nb][0] - mn0);
            float p1 = ex2(sc[nb][1] - mn0);
            float p2 = ex2(sc[nb][2] - mn1);
            float p3 = ex2(sc[nb][3] - mn1);
            l0 += p0 + p1;
            l1 += p2 + p3;
            sc[nb][0] = p0; sc[nb][1] = p1;
            sc[nb][2] = p2; sc[nb][3] = p3;
        }

        // --- O += P V : C-frag == A-frag after f16x2 pack ---
        #pragma unroll
        for (int kcc = 0; kcc < 4; kcc++) {
            uint32_t pa[4];
            pa[0] = packh2(sc[2 * kcc][0],     sc[2 * kcc][1]);
            pa[1] = packh2(sc[2 * kcc][2],     sc[2 * kcc][3]);
            pa[2] = packh2(sc[2 * kcc + 1][0], sc[2 * kcc + 1][1]);
            pa[3] = packh2(sc[2 * kcc + 1][2], sc[2 * kcc + 1][3]);
            uint32_t vb0[4], vb1[4];
            *(uint4*)vb0 = *(const uint4*)&Vh[buf][kcc * 8 + tig][g8 * 4];
            *(uint4*)vb1 = *(const uint4*)&Vh[buf][kcc * 8 + tig + 4][g8 * 4];
            #pragma unroll
            for (int nb = 0; nb < 4; nb++)
                mma_f16(o[nb], pa, vb0[nb], vb1[nb]);
        }
        __syncthreads();
    }

    // --- epilogue: normalize, write fp16 in proj-A permuted layout ---
    l0 += __shfl_xor_sync(0xffffffffu, l0, 1);
    l0 += __shfl_xor_sync(0xffffffffu, l0, 2);
    l1 += __shfl_xor_sync(0xffffffffu, l1, 1);
    l1 += __shfl_xor_sync(0xffffffffu, l1, 2);
    float inv0 = (l0 > 0.0f) ? (1.0f / l0) : 0.0f;
    float inv1 = (l1 > 0.0f) ? (1.0f / l1) : 0.0f;

    #pragma unroll
    for (int nb = 0; nb < 4; nb++) {
        // pair index p = head*16 + nb*4 + tig -> pos = head*16 + 4*tig + nb
        int pos = head * 16 + 4 * tig + nb;
        g_ah[qr0 * 128 + pos] = packh2(o[nb][0] * inv0, o[nb][1] * inv0);
        g_ah[qr1 * 128 + pos] = packh2(o[nb][2] * inv1, o[nb][3] * inv1);
    }
}

// ============================================================
extern "C" void kernel_launch(void* const* d_in, const int* in_sizes, int n_in,
                              void* d_out, int out_size) {
    const float* x      = (const float*)d_in[0];
    const float* dbz    = (const float*)d_in[1];
    const float* qkv_w  = (const float*)d_in[2];
    const float* proj_w = (const float*)d_in[3];
    const float* proj_b = (const float*)d_in[4];
    float* out = (float*)d_out;

    prep_kernel<<<2576, 256>>>(x, dbz, qkv_w, proj_w);
    gemm_h<0><<<dim3(768 / 64, N_TOK / 128), 256>>>(nullptr, nullptr, nullptr);
    flash_tc_kernel<<<dim3(N_TOK / 128, NH), 256>>>();
    gemm_h<1><<<dim3(CDIM / 64, N_TOK / 128), 256>>>(proj_b, x, out);
}

// round 16
// speedup vs baseline: 3.3879x; 1.0785x over previous
#include <cuda_runtime.h>
#include <cuda_fp16.h>
#include <math.h>
#include <stdint.h>

#define N_TOK 4096
#define CDIM 256
#define NH 8
#define HD 32
#define QSCALE (0.17677669529663687f * 1.4426950408889634f)  // 32^-0.5 * log2(e)

// ---- scratch (device globals) ----
__device__ uint32_t g_xh [N_TOK * 128];      // x fp16x2, frag-permuted
__device__ uint32_t g_qwh[768 * 128];        // qkv_w fp16x2 permuted
__device__ uint32_t g_pwh[CDIM * 128];       // proj_w fp16x2 permuted
__device__ uint32_t g_ah [N_TOK * 128];      // attention out fp16x2 permuted (proj A)
__device__ uint32_t g_qh [NH * N_TOK * 16];  // Q fp16x2 pairs, scaled
__device__ uint32_t g_kh [NH * N_TOK * 16];  // K fp16x2, B-frag perm
__device__ uint32_t g_vh [NH * 2048 * 32];   // V fp16x2 pairs across keys
__device__ float    g_kmask[N_TOK];          // 0.f kept, -1e30f dropped
__device__ uint32_t g_mkp[N_TOK / 2];        // packed pair AND-masks (lo/hi 0xFFFF per kept key)

#define XW (N_TOK * 128)
#define QW (768 * 128)
#define PW (CDIM * 128)
#define TOTC (XW + QW + PW)

// ============================================================
__device__ __forceinline__ float ex2(float x) {
    float r; asm("ex2.approx.ftz.f32 %0, %1;" : "=f"(r) : "f"(x)); return r;
}
__device__ __forceinline__ uint32_t ex2h2(uint32_t x) {
    uint32_t r; asm("ex2.approx.f16x2 %0, %1;" : "=r"(r) : "r"(x)); return r;
}
__device__ __forceinline__ uint32_t packh2(float lo, float hi) {
    __half2 h = __floats2half2_rn(lo, hi);
    return *(uint32_t*)&h;
}
__device__ __forceinline__ void mma_f16(float c[4], const uint32_t a[4],
                                        uint32_t b0, uint32_t b1) {
    asm volatile(
        "mma.sync.aligned.m16n8k16.row.col.f32.f16.f16.f32 "
        "{%0,%1,%2,%3},{%4,%5,%6,%7},{%8,%9},{%0,%1,%2,%3};"
        : "+f"(c[0]), "+f"(c[1]), "+f"(c[2]), "+f"(c[3])
        : "r"(a[0]), "r"(a[1]), "r"(a[2]), "r"(a[3]), "r"(b0), "r"(b1));
}
__device__ __forceinline__ void cp16(void* s, const void* g) {
    uint32_t sa = (uint32_t)__cvta_generic_to_shared(s);
    asm volatile("cp.async.cg.shared.global [%0], [%1], 16;\n" :: "r"(sa), "l"(g) : "memory");
}
__device__ __forceinline__ void cp_commit() { asm volatile("cp.async.commit_group;\n" ::: "memory"); }
__device__ __forceinline__ void cp_wait1()  { asm volatile("cp.async.wait_group 1;\n" ::: "memory"); }
__device__ __forceinline__ void cp_wait0()  { asm volatile("cp.async.wait_group 0;\n" ::: "memory"); }

__device__ __forceinline__ bool keepf(const float* dbz, int n) {
    int t = n >> 10, rem = n & 1023, y = rem >> 5, x0 = rem & 31;
    const float* d = dbz + t * 1024;
    bool k = false;
    #pragma unroll
    for (int dy = -1; dy <= 1; dy++) {
        int yy = y + dy;
        if (yy < 0 || yy >= 32) continue;
        #pragma unroll
        for (int dx = -1; dx <= 1; dx++) {
            int xx = x0 + dx;
            if (xx < 0 || xx >= 32) continue;
            k = k || (d[yy * 32 + xx] >= 15.0f);
        }
    }
    return k;
}

// ============================================================
// Prep: fp16-convert + fragment-permute x/qkv_w/proj_w; keep mask; pair masks.
// ============================================================
__global__ __launch_bounds__(256) void prep_kernel(
    const float* __restrict__ x, const float* __restrict__ dbz,
    const float* __restrict__ qkv_w, const float* __restrict__ proj_w)
{
    int idx = blockIdx.x * 256 + threadIdx.x;
    if (idx < TOTC) {
        const float* src; uint32_t* dst; int rel;
        if (idx < XW)           { src = x;      dst = g_xh;  rel = idx; }
        else if (idx < XW + QW) { src = qkv_w;  dst = g_qwh; rel = idx - XW; }
        else                    { src = proj_w; dst = g_pwh; rel = idx - XW - QW; }
        int row = rel >> 7, p = rel & 127;
        int gk = p >> 4, q = p & 15;
        int pos = (gk << 4) | ((q & 3) << 2) | (q >> 2);
        float2 v = *(const float2*)&src[row * 256 + p * 2];
        dst[(row << 7) + pos] = packh2(v.x, v.y);
    } else {
        int n = idx - TOTC;
        if (n < N_TOK) {
            g_kmask[n] = keepf(dbz, n) ? 0.0f : -1e30f;
        } else if (n < N_TOK + N_TOK / 2) {
            int j = n - N_TOK;
            bool k0 = keepf(dbz, 2 * j);
            bool k1 = keepf(dbz, 2 * j + 1);
            g_mkp[j] = (k0 ? 0x0000FFFFu : 0u) | (k1 ? 0xFFFF0000u : 0u);
        }
    }
}

// ============================================================
// fp16 GEMM, BK=64 (4 iters), cp.async double-buffered, group-major smem.
// CTA tile 128x64, 8 warps (4x2). MODE 0: qkv scatter. MODE 1: proj epilogue.
// ============================================================
template <int MODE>
__global__ __launch_bounds__(256, 2) void gemm_h(
    const float* __restrict__ bias, const float* __restrict__ xres,
    float* __restrict__ out)
{
    __shared__ __align__(16) uint32_t As[2][2][128][16];
    __shared__ __align__(16) uint32_t Bs[2][2][64][16];

    const uint32_t* Ag = (MODE == 0) ? g_xh : g_ah;
    const uint32_t* Bg = (MODE == 0) ? g_qwh : g_pwh;

    const int tid  = threadIdx.x;
    const int warp = tid >> 5;
    const int lane = tid & 31;
    const int grp  = lane >> 2;
    const int tig  = lane & 3;
    const int wm   = warp >> 1;
    const int wn   = warp & 1;
    const int row0 = blockIdx.y * 128;
    const int col0 = blockIdx.x * 64;

    float acc[2][4][4];
    #pragma unroll
    for (int mi = 0; mi < 2; mi++)
        #pragma unroll
        for (int ni = 0; ni < 4; ni++)
            #pragma unroll
            for (int j = 0; j < 4; j++) acc[mi][ni][j] = 0.0f;

    // ---- prologue stage (buf 0, kw=0): A 4 cp16, B 2 cp16 per thread ----
    {
        #pragma unroll
        for (int t = 0; t < 4; t++) {
            int i = tid + t * 256;
            int r = i >> 3, c = i & 7;
            cp16(&As[0][c >> 2][r][(c & 3) * 4], Ag + (row0 + r) * 128 + c * 4);
        }
        #pragma unroll
        for (int t = 0; t < 2; t++) {
            int i = tid + t * 256;
            int r = i >> 3, c = i & 7;
            cp16(&Bs[0][c >> 2][r][(c & 3) * 4], Bg + (col0 + r) * 128 + c * 4);
        }
        cp_commit();
    }

    #pragma unroll
    for (int it = 0; it < 4; it++) {
        const int buf = it & 1;
        if (it + 1 < 4) {
            const int nb1 = buf ^ 1;
            const int kw = (it + 1) * 32;
            #pragma unroll
            for (int t = 0; t < 4; t++) {
                int i = tid + t * 256;
                int r = i >> 3, c = i & 7;
                cp16(&As[nb1][c >> 2][r][(c & 3) * 4], Ag + (row0 + r) * 128 + kw + c * 4);
            }
            #pragma unroll
            for (int t = 0; t < 2; t++) {
                int i = tid + t * 256;
                int r = i >> 3, c = i & 7;
                cp16(&Bs[nb1][c >> 2][r][(c & 3) * 4], Bg + (col0 + r) * 128 + kw + c * 4);
            }
            cp_commit();
            cp_wait1();
        } else {
            cp_wait0();
        }
        __syncthreads();

        #pragma unroll
        for (int g = 0; g < 2; g++) {
            uint32_t wa[2][2][4], wb[4][4];
            #pragma unroll
            for (int mi = 0; mi < 2; mi++) {
                int r = wm * 32 + mi * 16 + grp;
                *(uint4*)wa[mi][0] = *(const uint4*)&As[buf][g][r][tig * 4];
                *(uint4*)wa[mi][1] = *(const uint4*)&As[buf][g][r + 8][tig * 4];
            }
            #pragma unroll
            for (int ni = 0; ni < 4; ni++) {
                int rb = wn * 32 + ni * 8 + grp;
                *(uint4*)wb[ni] = *(const uint4*)&Bs[buf][g][rb][tig * 4];
            }
            #pragma unroll
            for (int c = 0; c < 2; c++)
                #pragma unroll
                for (int mi = 0; mi < 2; mi++) {
                    uint32_t a[4] = {wa[mi][0][c * 2], wa[mi][1][c * 2],
                                     wa[mi][0][c * 2 + 1], wa[mi][1][c * 2 + 1]};
                    #pragma unroll
                    for (int ni = 0; ni < 4; ni++)
                        mma_f16(acc[mi][ni], a, wb[ni][c * 2], wb[ni][c * 2 + 1]);
                }
        }
        __syncthreads();
    }

    // ---- epilogue ----
    #pragma unroll
    for (int mi = 0; mi < 2; mi++) {
        int rA = row0 + wm * 32 + mi * 16 + grp;
        #pragma unroll
        for (int half = 0; half < 2; half++) {
            int n = rA + half * 8;
            #pragma unroll
            for (int ni = 0; ni < 4; ni++) {
                int c = col0 + wn * 32 + ni * 8 + 2 * tig;
                float v0 = acc[mi][ni][half * 2 + 0];
                float v1 = acc[mi][ni][half * 2 + 1];
                if (MODE == 0) {
                    int part = c >> 8;
                    int cc   = c & 255;
                    int hh   = cc >> 5;
                    int dd   = cc & 31;       // even
                    if (part == 0) {
                        g_qh[(hh * N_TOK + n) * 16 + (dd >> 1)] =
                            packh2(v0 * QSCALE, v1 * QSCALE);
                    } else if (part == 1) {
                        int p = dd >> 1;
                        int pos = ((p & 3) << 2) | (p >> 2);
                        g_kh[(hh * N_TOK + n) * 16 + pos] = packh2(v0, v1);
                    } else {
                        int j   = n >> 1;
                        int par = n & 1;
                        int pos0 = ((dd & 7) << 2) | (dd >> 3);
                        int dd1  = dd + 1;
                        int pos1 = ((dd1 & 7) << 2) | (dd1 >> 3);
                        uint16_t* vp = (uint16_t*)g_vh;
                        int base = (hh * 2048 + j) * 32;
                        __half h0 = __float2half_rn(v0);
                        __half h1 = __float2half_rn(v1);
                        vp[(base + pos0) * 2 + par] = *(uint16_t*)&h0;
                        vp[(base + pos1) * 2 + par] = *(uint16_t*)&h1;
                    }
                } else {
                    bool keep = (g_kmask[n] == 0.0f);
                    float2 bv = *(const float2*)&bias[c];
                    float2 xr = *(const float2*)&xres[n * CDIM + c];
                    float o0 = (keep ? (v0 + bv.x) : 0.0f) + xr.x;
                    float o1 = (keep ? (v1 + bv.y) : 0.0f) + xr.y;
                    *(float2*)&out[n * CDIM + c] = make_float2(o0, o1);
                }
            }
        }
    }
}

// ============================================================
// Flash attention: fp16 k16, 128-key staged tiles (2x64 halves),
// f16x2 exp, mask-AND on p, l-via-MMA. Grid (32, 8), 256 threads.
// ============================================================
#define NTILES 32
#define ONES2 0x3C003C00u

__global__ __launch_bounds__(256, 2) void flash_tc_kernel() {
    const int head = blockIdx.y;
    const int qt   = blockIdx.x * 128;
    const int tid  = threadIdx.x;
    const int warp = tid >> 5;
    const int lane = tid & 31;
    const int g8   = lane >> 2;
    const int tig  = lane & 3;

    __shared__ __align__(16) uint32_t Kh[2][128][16];  // 16KB
    __shared__ __align__(16) uint32_t Vh[2][64][40];   // 20KB
    __shared__ __align__(16) uint32_t mkp[2][64];

    const uint32_t* QH = g_qh + head * N_TOK * 16;
    const uint32_t* KH = g_kh + head * N_TOK * 16;
    const uint32_t* VH = g_vh + head * 2048 * 32;

    // --- Q A-fragments (fp16, pre-scaled, one-time) ---
    const int qr0 = qt + warp * 16 + g8;
    const int qr1 = qr0 + 8;
    uint32_t qa[2][4];
    #pragma unroll
    for (int kc = 0; kc < 2; kc++) {
        qa[kc][0] = QH[qr0 * 16 + kc * 8 + tig];
        qa[kc][1] = QH[qr1 * 16 + kc * 8 + tig];
        qa[kc][2] = QH[qr0 * 16 + kc * 8 + tig + 4];
        qa[kc][3] = QH[qr1 * 16 + kc * 8 + tig + 4];
    }

    float m0 = -1e30f, m1 = -1e30f;
    float o[4][4], lacc[4];
    #pragma unroll
    for (int nb = 0; nb < 4; nb++)
        #pragma unroll
        for (int j = 0; j < 4; j++) o[nb][j] = 0.0f;
    lacc[0] = lacc[1] = lacc[2] = lacc[3] = 0.0f;

    // ---- prologue stage (buf 0, tile 0) ----
    {
        #pragma unroll
        for (int t = 0; t < 2; t++) {
            int i = tid + t * 256;
            cp16(&Kh[0][i >> 2][(i & 3) * 4], KH + (i >> 2) * 16 + (i & 3) * 4);
            cp16(&Vh[0][i >> 3][(i & 7) * 4], VH + (i >> 3) * 32 + (i & 7) * 4);
        }
        if (tid < 16) cp16(&mkp[0][tid * 4], g_mkp + tid * 4);
        cp_commit();
    }

    for (int it = 0; it < NTILES; it++) {
        const int buf = it & 1;
        if (it + 1 < NTILES) {
            const int nb1 = buf ^ 1;
            const int kr = (it + 1) * 128;
            const int vr = (it + 1) * 64;
            #pragma unroll
            for (int t = 0; t < 2; t++) {
                int i = tid + t * 256;
                cp16(&Kh[nb1][i >> 2][(i & 3) * 4], KH + (kr + (i >> 2)) * 16 + (i & 3) * 4);
                cp16(&Vh[nb1][i >> 3][(i & 7) * 4], VH + (vr + (i >> 3)) * 32 + (i & 7) * 4);
            }
            if (tid < 16) cp16(&mkp[nb1][tid * 4], g_mkp + vr + tid * 4);
            cp_commit();
            cp_wait1();
        } else {
            cp_wait0();
        }
        __syncthreads();

        #pragma unroll
        for (int h = 0; h < 2; h++) {
            // --- S = Q K^T (64 keys, unmasked) ---
            float sc[8][4];
            #pragma unroll
            for (int nbk = 0; nbk < 8; nbk++) {
                uint32_t kb[4];
                *(uint4*)kb = *(const uint4*)&Kh[buf][h * 64 + nbk * 8 + g8][tig * 4];
                sc[nbk][0] = sc[nbk][1] = sc[nbk][2] = sc[nbk][3] = 0.0f;
                mma_f16(sc[nbk], qa[0], kb[0], kb[1]);
                mma_f16(sc[nbk], qa[1], kb[2], kb[3]);
            }

            // --- online softmax (log2 domain, unmasked max) ---
            float rm0 = -1e30f, rm1 = -1e30f;
            #pragma unroll
            for (int nb = 0; nb < 8; nb++) {
                rm0 = fmaxf(rm0, fmaxf(sc[nb][0], sc[nb][1]));
                rm1 = fmaxf(rm1, fmaxf(sc[nb][2], sc[nb][3]));
            }
            rm0 = fmaxf(rm0, __shfl_xor_sync(0xffffffffu, rm0, 1));
            rm0 = fmaxf(rm0, __shfl_xor_sync(0xffffffffu, rm0, 2));
            rm1 = fmaxf(rm1, __shfl_xor_sync(0xffffffffu, rm1, 1));
            rm1 = fmaxf(rm1, __shfl_xor_sync(0xffffffffu, rm1, 2));

            float mn0 = fmaxf(m0, rm0);
            float mn1 = fmaxf(m1, rm1);
            float corr0 = ex2(m0 - mn0);
            float corr1 = ex2(m1 - mn1);
            m0 = mn0; m1 = mn1;
            #pragma unroll
            for (int nb = 0; nb < 4; nb++) {
                o[nb][0] *= corr0; o[nb][1] *= corr0;
                o[nb][2] *= corr1; o[nb][3] *= corr1;
            }
            lacc[0] *= corr0; lacc[1] *= corr0;
            lacc[2] *= corr1; lacc[3] *= corr1;

            // --- p = 2^(S-m) in fp16x2, masked by AND ---
            uint32_t ph[8][2];
            #pragma unroll
            for (int nb = 0; nb < 8; nb++) {
                uint32_t mp = mkp[buf][h * 32 + nb * 4 + tig];
                ph[nb][0] = ex2h2(packh2(sc[nb][0] - mn0, sc[nb][1] - mn0)) & mp;
                ph[nb][1] = ex2h2(packh2(sc[nb][2] - mn1, sc[nb][3] - mn1)) & mp;
            }

            // --- O += P V, l += P 1 ---
            #pragma unroll
            for (int kcc = 0; kcc < 4; kcc++) {
                uint32_t pa[4] = {ph[2 * kcc][0], ph[2 * kcc][1],
                                  ph[2 * kcc + 1][0], ph[2 * kcc + 1][1]};
                uint32_t vb0[4], vb1[4];
                *(uint4*)vb0 = *(const uint4*)&Vh[buf][h * 32 + kcc * 8 + tig][g8 * 4];
                *(uint4*)vb1 = *(const uint4*)&Vh[buf][h * 32 + kcc * 8 + tig + 4][g8 * 4];
                #pragma unroll
                for (int nb = 0; nb < 4; nb++)
                    mma_f16(o[nb], pa, vb0[nb], vb1[nb]);
                mma_f16(lacc, pa, ONES2, ONES2);
            }
        }
        __syncthreads();
    }

    // --- epilogue: l from MMA accumulator (all columns identical) ---
    float l0 = lacc[0], l1 = lacc[2];
    float inv0 = (l0 > 0.0f) ? (1.0f / l0) : 0.0f;
    float inv1 = (l1 > 0.0f) ? (1.0f / l1) : 0.0f;

    #pragma unroll
    for (int nb = 0; nb < 4; nb++) {
        int pos = head * 16 + 4 * tig + nb;
        g_ah[qr0 * 128 + pos] = packh2(o[nb][0] * inv0, o[nb][1] * inv0);
        g_ah[qr1 * 128 + pos] = packh2(o[nb][2] * inv1, o[nb][3] * inv1);
    }
}

// ============================================================
extern "C" void kernel_launch(void* const* d_in, const int* in_sizes, int n_in,
                              void* d_out, int out_size) {
    const float* x      = (const float*)d_in[0];
    const float* dbz    = (const float*)d_in[1];
    const float* qkv_w  = (const float*)d_in[2];
    const float* proj_w = (const float*)d_in[3];
    const float* proj_b = (const float*)d_in[4];
    float* out = (float*)d_out;

    prep_kernel<<<(TOTC + N_TOK + N_TOK / 2 + 255) / 256, 256>>>(x, dbz, qkv_w, proj_w);
    gemm_h<0><<<dim3(768 / 64, N_TOK / 128), 256>>>(nullptr, nullptr, nullptr);
    flash_tc_kernel<<<dim3(N_TOK / 128, NH), 256>>>();
    gemm_h<1><<<dim3(CDIM / 64, N_TOK / 128), 256>>>(proj_b, x, out);
}